// round 3
// baseline (speedup 1.0000x reference)
#include <cuda_runtime.h>

#define NQ 2048
#define NK 2048
#define NH 8
#define DH 64
#define QT 8          // q-rows per block in the softmax kernel

// Scratch: exp(sq) and exp(sk), 2048x8 floats each (64 KB each).
__device__ float g_esq[NQ * NH];
__device__ float g_esk[NK * NH];

// One block per row (first NQ blocks -> q, next NK -> k).
// 256 threads = 8 warps; warp h reduces the 64-elem dot for head h.
__global__ void __launch_bounds__(256) proj_kernel(
    const float* __restrict__ q,
    const float* __restrict__ k,
    const float* __restrict__ attn)
{
    int row = blockIdx.x;
    const float* src;
    int koff;
    float* dst;
    if (row < NQ) {
        src  = q + (size_t)row * (NH * DH);
        koff = 0;
        dst  = g_esq + row * NH;
    } else {
        int r = row - NQ;
        src  = k + (size_t)r * (NH * DH);
        koff = DH;
        dst  = g_esk + r * NH;
    }

    int tid  = threadIdx.x;       // 0..255
    int h    = tid >> 5;          // warp id = head id
    int lane = tid & 31;

    // Row is 512 contiguous floats: [h][d]. Thread covers elems 2*tid, 2*tid+1.
    float2 v = ((const float2*)src)[tid];
    // attn layout: (1, NH, 2*DH): a_q at [h][0:64], a_k at [h][64:128]
    float2 c = *(const float2*)(attn + h * (2 * DH) + koff + lane * 2);

    float s = v.x * c.x + v.y * c.y;
    #pragma unroll
    for (int off = 16; off; off >>= 1)
        s += __shfl_xor_sync(0xffffffffu, s, off);

    if (lane == 0) dst[h] = __expf(s);
}

// Grid: (NK/256, NQ/QT). Thread owns one k, iterates QT q-rows.
// esk held in registers; esq read as uniform LDS.128 (2 per iter, broadcast)
// to keep L1 wavefronts near the store-only floor.
__global__ void __launch_bounds__(256) softmax_kernel(float* __restrict__ out)
{
    int qi0 = blockIdx.y * QT;
    int kk  = blockIdx.x * 256 + threadIdx.x;

    __shared__ float4 s_eq[QT * 2];     // QT rows x 8 heads, as float4 pairs
    if (threadIdx.x < QT * 2)
        s_eq[threadIdx.x] = ((const float4*)(g_esq + qi0 * NH))[threadIdx.x];
    __syncthreads();

    const float4* ekp = (const float4*)(g_esk + kk * NH);
    float4 a = __ldg(ekp);
    float4 b = __ldg(ekp + 1);

    float4* op = (float4*)(out + ((size_t)qi0 * NK + kk) * NH);

    #pragma unroll
    for (int i = 0; i < QT; i++) {
        float4 ea = s_eq[2 * i];        // uniform -> LDS.128 broadcast (1 wf)
        float4 eb = s_eq[2 * i + 1];

        // exp(relu(sq+sk)) == max(exp(sq)*exp(sk), 1)
        float p0 = fmaxf(ea.x * a.x, 1.0f);
        float p1 = fmaxf(ea.y * a.y, 1.0f);
        float p2 = fmaxf(ea.z * a.z, 1.0f);
        float p3 = fmaxf(ea.w * a.w, 1.0f);
        float p4 = fmaxf(eb.x * b.x, 1.0f);
        float p5 = fmaxf(eb.y * b.y, 1.0f);
        float p6 = fmaxf(eb.z * b.z, 1.0f);
        float p7 = fmaxf(eb.w * b.w, 1.0f);

        float sum = ((p0 + p1) + (p2 + p3)) + ((p4 + p5) + (p6 + p7));
        float inv = __fdividef(1.0f, sum);

        op[0] = make_float4(p0 * inv, p1 * inv, p2 * inv, p3 * inv);
        op[1] = make_float4(p4 * inv, p5 * inv, p6 * inv, p7 * inv);

        op += (size_t)NK * NH / 4;
    }
}

extern "C" void kernel_launch(void* const* d_in, const int* in_sizes, int n_in,
                              void* d_out, int out_size)
{
    const float* q    = (const float*)d_in[0];
    const float* k    = (const float*)d_in[1];
    const float* attn = (const float*)d_in[2];
    float* out = (float*)d_out;

    proj_kernel<<<NQ + NK, 256>>>(q, k, attn);

    dim3 grid(NK / 256, NQ / QT);
    softmax_kernel<<<grid, 256>>>(out);
}

// round 8
// speedup vs baseline: 1.1096x; 1.1096x over previous
#include <cuda_runtime.h>

#define NQ 2048
#define NK 2048
#define NH 8
#define DH 64
#define PROJ_ROWS 8   // rows per proj block

// Scratch: exp(sq) and exp(sk), 2048x8 floats each (64 KB each).
// 256-B aligned so every row (k*32 B) satisfies v8.f32's 32-B alignment.
__device__ __align__(256) float g_esq[NQ * NH];
__device__ __align__(256) float g_esk[NK * NH];

// 256-bit global load/store (sm_100+): one instruction per 8 floats.
__device__ __forceinline__ void ldg256(float* r, const float* p) {
    asm volatile("ld.global.v8.f32 {%0,%1,%2,%3,%4,%5,%6,%7}, [%8];"
        : "=f"(r[0]), "=f"(r[1]), "=f"(r[2]), "=f"(r[3]),
          "=f"(r[4]), "=f"(r[5]), "=f"(r[6]), "=f"(r[7])
        : "l"(p));
}
__device__ __forceinline__ void stg256(float* p, const float* r) {
    asm volatile("st.global.v8.f32 [%0], {%1,%2,%3,%4,%5,%6,%7,%8};"
        :: "l"(p),
           "f"(r[0]), "f"(r[1]), "f"(r[2]), "f"(r[3]),
           "f"(r[4]), "f"(r[5]), "f"(r[6]), "f"(r[7])
        : "memory");
}

// Block handles PROJ_ROWS rows (all-q or all-k since 8 | 2048).
// Warp h reduces the 64-elem dot for head h; attn coeffs loaded once.
__global__ void __launch_bounds__(256) proj_kernel(
    const float* __restrict__ q,
    const float* __restrict__ k,
    const float* __restrict__ attn)
{
    int base = blockIdx.x * PROJ_ROWS;
    const float* src;
    int koff;
    float* dst;
    if (base < NQ) {
        src  = q + (size_t)base * (NH * DH);
        koff = 0;
        dst  = g_esq + base * NH;
    } else {
        int r = base - NQ;
        src  = k + (size_t)r * (NH * DH);
        koff = DH;
        dst  = g_esk + r * NH;
    }

    int tid  = threadIdx.x;
    int h    = tid >> 5;
    int lane = tid & 31;

    // attn layout (1, NH, 2*DH): a_q at [h][0:64], a_k at [h][64:128]
    float2 c = *(const float2*)(attn + h * (2 * DH) + koff + lane * 2);

    #pragma unroll
    for (int r = 0; r < PROJ_ROWS; r++) {
        float2 v = ((const float2*)(src + (size_t)r * (NH * DH)))[tid];
        float s = v.x * c.x + v.y * c.y;
        #pragma unroll
        for (int off = 16; off; off >>= 1)
            s += __shfl_xor_sync(0xffffffffu, s, off);
        if (lane == 0) dst[r * NH + h] = __expf(s);
    }
}

// Grid: (NK/512, NQ). Thread owns k0 = bx*256+tid and k1 = k0+1024.
// One LDG.256 per esk row, one STG.256 per output row: minimal LSU issue cost.
__global__ void __launch_bounds__(256) softmax_kernel(float* __restrict__ out)
{
    int qi = blockIdx.y;
    int k0 = blockIdx.x * 256 + threadIdx.x;
    int k1 = k0 + (NK / 2);

    __shared__ float4 s_eq[2];
    if (threadIdx.x < 2)
        s_eq[threadIdx.x] = ((const float4*)(g_esq + qi * NH))[threadIdx.x];
    __syncthreads();

    float ek0[8], ek1[8];
    ldg256(ek0, g_esk + k0 * NH);
    ldg256(ek1, g_esk + k1 * NH);

    float4 ea = s_eq[0];                 // uniform LDS.128 broadcast
    float4 eb = s_eq[1];
    float eq[8] = {ea.x, ea.y, ea.z, ea.w, eb.x, eb.y, eb.z, eb.w};

    float* ob = out + ((size_t)qi * NK) * NH;

    // exp(relu(sq+sk)) == max(exp(sq)*exp(sk), 1)
    {
        float p[8];
        #pragma unroll
        for (int i = 0; i < 8; i++) p[i] = fmaxf(eq[i] * ek0[i], 1.0f);
        float sum = ((p[0]+p[1])+(p[2]+p[3])) + ((p[4]+p[5])+(p[6]+p[7]));
        float inv = __fdividef(1.0f, sum);
        #pragma unroll
        for (int i = 0; i < 8; i++) p[i] *= inv;
        stg256(ob + (size_t)k0 * NH, p);
    }
    {
        float p[8];
        #pragma unroll
        for (int i = 0; i < 8; i++) p[i] = fmaxf(eq[i] * ek1[i], 1.0f);
        float sum = ((p[0]+p[1])+(p[2]+p[3])) + ((p[4]+p[5])+(p[6]+p[7]));
        float inv = __fdividef(1.0f, sum);
        #pragma unroll
        for (int i = 0; i < 8; i++) p[i] *= inv;
        stg256(ob + (size_t)k1 * NH, p);
    }
}

extern "C" void kernel_launch(void* const* d_in, const int* in_sizes, int n_in,
                              void* d_out, int out_size)
{
    const float* q    = (const float*)d_in[0];
    const float* k    = (const float*)d_in[1];
    const float* attn = (const float*)d_in[2];
    float* out = (float*)d_out;

    proj_kernel<<<(NQ + NK) / PROJ_ROWS, 256>>>(q, k, attn);

    dim3 grid(NK / 512, NQ);
    softmax_kernel<<<grid, 256>>>(out);
}